// round 6
// baseline (speedup 1.0000x reference)
#include <cuda_runtime.h>
#include <cuda_fp16.h>

#define D 128
#define ALPHA 0.1f
#define BETA 0.22314355131420976f        /* log(1.25) */
#define ONE_MB 0.7768564486857909f       /* 1 - BETA */
#define MAXN 50000
#define MAXE 600000
#define NB 296                           /* build-kernel grid: 2 blocks/SM, co-resident */
#define BT 256                           /* build-kernel block */

__device__ int      g_deg[MAXN];         // zero at load; re-zeroed every launch
__device__ int      g_off[MAXN + 1];
__device__ int      g_cursor[MAXN];
__device__ int      g_csrc[MAXE];
__device__ float    g_norm[MAXN];
__device__ float    g_h[MAXN * D];
__device__ uint2    g_feath[MAXN * 32];  // fp16 prescaled feat (row = 32 x uint2 = 128 halfs)
__device__ int      g_bsum[NB];
__device__ uint2    g_wperm[16 * 16 * 32];
__device__ unsigned g_bar1, g_bar2, g_bar3, g_done_ctr;

__device__ __forceinline__ unsigned f2tf32(float f) {
    unsigned r;
    asm("cvt.rna.tf32.f32 %0, %1;" : "=r"(r) : "f"(f));
    return r;
}

__device__ __forceinline__ void grid_barrier(unsigned* ctr, unsigned nb) {
    __syncthreads();
    __threadfence();
    if (threadIdx.x == 0) {
        atomicAdd(ctr, 1u);
        while (*(volatile unsigned*)ctr < nb) { }
    }
    __syncthreads();
    __threadfence();
}

// ---- ONE persistent kernel: wconv + deg -> scan(+norm) -> offsets -> permute + prescale ----
__global__ __launch_bounds__(BT) void build_kernel(const int* __restrict__ src,
                                                   const int* __restrict__ dst,
                                                   const float* __restrict__ W,
                                                   const float* __restrict__ feat,
                                                   int ne, int n) {
    __shared__ int s[BT];
    __shared__ int wsum[BT / 32];
    const int tid = threadIdx.x;
    const int bid = blockIdx.x;
    const int gtid = bid * BT + tid;
    const int gstride = NB * BT;

    // phase 0: W -> tf32 B-fragment permutation (independent; blocks 0..31)
    if (bid < 32) {
        int t = bid * BT + tid;          // 8192 lanes
        int lane = t & 31, tile = t >> 5;
        int nt = tile & 15, kt = tile >> 4;
        int k = kt * 8 + (lane & 3);
        int nn = nt * 8 + (lane >> 2);
        uint2 b;
        b.x = f2tf32(W[k * D + nn]);
        b.y = f2tf32(W[(k + 4) * D + nn]);
        g_wperm[tile * 32 + lane] = b;
    }

    // phase 1: degree count
    for (int e = gtid; e < ne; e += gstride)
        atomicAdd(&g_deg[dst[e]], 1);

    grid_barrier(&g_bar1, NB);

    // phase 2a: block-local exclusive scan over this block's node chunk + norm
    const int C = (n + NB - 1) / NB;     // 169 for n=50000
    const int beg = bid * C;
    const int cnt = min(C, n - beg);     // may be <=0 for tail blocks
    int v = 0;
    if (tid < cnt) v = g_deg[beg + tid];
    s[tid] = v;
    __syncthreads();
    #pragma unroll
    for (int off = 1; off < BT; off <<= 1) {
        int t2 = (tid >= off) ? s[tid - off] : 0;
        __syncthreads();
        s[tid] += t2;
        __syncthreads();
    }
    if (tid < cnt) {
        g_off[beg + tid] = s[tid] - v;   // local exclusive
        g_norm[beg + tid] = rsqrtf(fmaxf((float)v, 1.0f));
    }
    if (tid == BT - 1) g_bsum[bid] = (cnt > 0) ? s[BT - 1] : 0;

    grid_barrier(&g_bar2, NB);

    // phase 2b: prefix = sum of bsum[0..bid-1]; write global offsets + cursors
    {
        int acc = 0;
        for (int j = tid; j < bid; j += BT) acc += g_bsum[j];
        #pragma unroll
        for (int o = 16; o > 0; o >>= 1) acc += __shfl_down_sync(0xffffffffu, acc, o);
        if ((tid & 31) == 0) wsum[tid >> 5] = acc;
        __syncthreads();
        int prefix = 0;
        #pragma unroll
        for (int j = 0; j < BT / 32; j++) prefix += wsum[j];
        if (tid < cnt) {
            int o = g_off[beg + tid] + prefix;
            g_off[beg + tid] = o;
            g_cursor[beg + tid] = o;
        }
        if (gtid == 0) g_off[n] = ne;
    }

    grid_barrier(&g_bar3, NB);

    // phase 3: permute edges into CSR; prescale feat*norm -> fp16; re-zero deg
    for (int e = gtid; e < ne; e += gstride) {
        int d = dst[e];
        int pos = atomicAdd(&g_cursor[d], 1);
        g_csrc[pos] = src[e];
    }
    for (int i = gtid; i < n * 32; i += gstride) {     // one float4 -> half4
        int row = i >> 5;
        float nm = g_norm[row];
        float4 fv = __ldg((const float4*)feat + i);
        __half2 h0 = __floats2half2_rn(fv.x * nm, fv.y * nm);
        __half2 h1 = __floats2half2_rn(fv.z * nm, fv.w * nm);
        uint2 p;
        p.x = *(unsigned*)&h0;
        p.y = *(unsigned*)&h1;
        g_feath[i] = p;
    }
    for (int i = gtid; i < n; i += gstride) g_deg[i] = 0;

    // cleanup: last block to finish resets barrier counters (graph-replay safe)
    __syncthreads();
    __threadfence();
    if (tid == 0) {
        unsigned dcount = atomicAdd(&g_done_ctr, 1u);
        if (dcount == NB - 1) {
            g_bar1 = 0; g_bar2 = 0; g_bar3 = 0; g_done_ctr = 0;
            __threadfence();
        }
    }
}

// ---- aggregation: one warp per destination row, fp16 prescaled gathers (256B/row) ----
__global__ __launch_bounds__(256) void agg_kernel(const float* __restrict__ feat0, int n) {
    int w    = (blockIdx.x * blockDim.x + threadIdx.x) >> 5;
    int lane = threadIdx.x & 31;
    if (w >= n) return;
    int beg = g_off[w];
    int end = g_off[w + 1];

    float4 acc = make_float4(0.f, 0.f, 0.f, 0.f);
    for (int j0 = beg; j0 < end; j0 += 32) {
        int jj = j0 + lane;
        int s = (jj < end) ? g_csrc[jj] : 0;
        int m = min(32, end - j0);
        for (int e = 0; e < m; e++) {
            int ss = __shfl_sync(0xffffffffu, s, e);
            uint2 p = __ldg(g_feath + (size_t)ss * 32 + lane);
            float2 f0 = __half22float2(*(__half2*)&p.x);
            float2 f1 = __half22float2(*(__half2*)&p.y);
            acc.x += f0.x; acc.y += f0.y; acc.z += f1.x; acc.w += f1.y;
        }
    }
    float nmd = g_norm[w] * (1.0f - ALPHA);
    float4 f0 = __ldg((const float4*)feat0 + (size_t)w * 32 + lane);
    float4 h;
    h.x = acc.x * nmd + f0.x * ALPHA;
    h.y = acc.y * nmd + f0.y * ALPHA;
    h.z = acc.z * nmd + f0.z * ALPHA;
    h.w = acc.w * nmd + f0.w * ALPHA;
    ((float4*)g_h)[(size_t)w * 32 + lane] = h;
}

// ---- tensor-core GEMM: mma.sync.m16n8k8 tf32, fp32 accumulate ----
#define GROWS 64
#define SH_PAD 132
__global__ __launch_bounds__(128) void mma_kernel(const float* __restrict__ bias,
                                                  float* __restrict__ out, int n) {
    __shared__ float sh[GROWS][SH_PAD];
    const int tid  = threadIdx.x;
    const int w    = tid >> 5;
    const int lane = tid & 31;
    const int r0   = blockIdx.x * GROWS;

    {
        int r = tid >> 1, half = tid & 1;
        int row = r0 + r;
        const float4* srcp = (const float4*)(g_h + (size_t)row * D) + half * 16;
        #pragma unroll
        for (int i = 0; i < 16; i++) {
            float4 v = (row < n) ? __ldg(srcp + i) : make_float4(0.f, 0.f, 0.f, 0.f);
            *(float4*)&sh[r][half * 64 + i * 4] = v;
        }
    }
    __syncthreads();

    float acc[16][4];
    #pragma unroll
    for (int nt = 0; nt < 16; nt++)
        #pragma unroll
        for (int i = 0; i < 4; i++) acc[nt][i] = 0.f;

    const int ra = w * 16 + (lane >> 2);
    const int ca = lane & 3;

    #pragma unroll
    for (int kt = 0; kt < 16; kt++) {
        unsigned a0 = f2tf32(sh[ra][kt * 8 + ca]);
        unsigned a1 = f2tf32(sh[ra + 8][kt * 8 + ca]);
        unsigned a2 = f2tf32(sh[ra][kt * 8 + ca + 4]);
        unsigned a3 = f2tf32(sh[ra + 8][kt * 8 + ca + 4]);
        const uint2* bp = g_wperm + (kt * 16) * 32 + lane;
        #pragma unroll
        for (int nt = 0; nt < 16; nt++) {
            uint2 b = __ldg(bp + nt * 32);
            asm volatile(
                "mma.sync.aligned.m16n8k8.row.col.f32.tf32.tf32.f32 "
                "{%0,%1,%2,%3}, {%4,%5,%6,%7}, {%8,%9}, {%0,%1,%2,%3};"
                : "+f"(acc[nt][0]), "+f"(acc[nt][1]),
                  "+f"(acc[nt][2]), "+f"(acc[nt][3])
                : "r"(a0), "r"(a1), "r"(a2), "r"(a3), "r"(b.x), "r"(b.y));
        }
    }

    const int lr   = w * 16 + (lane >> 2);
    const int row0 = r0 + lr;
    const int col0 = (lane & 3) * 2;
    #pragma unroll
    for (int nt = 0; nt < 16; nt++) {
        int col = nt * 8 + col0;
        float b0 = __ldg(&bias[col]);
        float b1 = __ldg(&bias[col + 1]);
        if (row0 < n) {
            float2 o;
            o.x = ONE_MB * sh[lr][col]     + BETA * acc[nt][0] + b0;
            o.y = ONE_MB * sh[lr][col + 1] + BETA * acc[nt][1] + b1;
            *(float2*)&out[(size_t)row0 * D + col] = o;
        }
        if (row0 + 8 < n) {
            float2 o;
            o.x = ONE_MB * sh[lr + 8][col]     + BETA * acc[nt][2] + b0;
            o.y = ONE_MB * sh[lr + 8][col + 1] + BETA * acc[nt][3] + b1;
            *(float2*)&out[(size_t)(row0 + 8) * D + col] = o;
        }
    }
}

extern "C" void kernel_launch(void* const* d_in, const int* in_sizes, int n_in,
                              void* d_out, int out_size) {
    const float* feat  = (const float*)d_in[0];
    const float* feat0 = (const float*)d_in[1];
    const float* W     = (const float*)d_in[2];
    const float* bias  = (const float*)d_in[3];
    const int*   src   = (const int*)d_in[4];
    const int*   dst   = (const int*)d_in[5];
    float* out = (float*)d_out;

    int n  = in_sizes[0] / D;
    int ne = in_sizes[4];

    build_kernel<<<NB, BT>>>(src, dst, W, feat, ne, n);

    int agg_blocks = (n * 32 + 255) / 256;   // one warp per row
    agg_kernel<<<agg_blocks, 256>>>(feat0, n);

    mma_kernel<<<(n + GROWS - 1) / GROWS, 128>>>(bias, out, n);
}

// round 8
// speedup vs baseline: 1.1128x; 1.1128x over previous
#include <cuda_runtime.h>
#include <cuda_fp16.h>

#define D 128
#define ALPHA 0.1f
#define BETA 0.22314355131420976f        /* log(1.25) */
#define ONE_MB 0.7768564486857909f       /* 1 - BETA */
#define MAXN 50000
#define MAXE 600000
#define SCAN_B 256

__device__ int   g_deg[MAXN];            // zero at load; re-zeroed every call
__device__ int   g_off[MAXN + 1];
__device__ int   g_cursor[MAXN];
__device__ int   g_csrc[MAXE];
__device__ float g_norm[MAXN];
__device__ float g_h[MAXN * D];
__device__ uint2 g_feath[MAXN * 32];     // fp16 prescaled feat: row = 32 uint2 = 128 halfs
__device__ int   g_bsum[SCAN_B];
__device__ uint2 g_wperm[16 * 16 * 32];

__device__ __forceinline__ unsigned f2tf32(float f) {
    unsigned r;
    asm("cvt.rna.tf32.f32 %0, %1;" : "=r"(r) : "f"(f));
    return r;
}

// degree count; blocks 0..31 also permute W into tf32 B-fragment order
__global__ void deg_kernel(const int* __restrict__ dst,
                           const float* __restrict__ W, int ne) {
    int e = blockIdx.x * blockDim.x + threadIdx.x;
    if (blockIdx.x < 32) {
        int t = e;                        // 8192 lanes
        int lane = t & 31, tile = t >> 5;
        int nt = tile & 15, kt = tile >> 4;
        int k = kt * 8 + (lane & 3);
        int nn = nt * 8 + (lane >> 2);
        uint2 b;
        b.x = f2tf32(W[k * D + nn]);
        b.y = f2tf32(W[(k + 4) * D + nn]);
        g_wperm[tile * 32 + lane] = b;
    }
    if (e < ne) atomicAdd(&g_deg[dst[e]], 1);
}

// block-local exclusive scan + norm
__global__ void scan_block_kernel(int n) {
    __shared__ int s[SCAN_B];
    int i = blockIdx.x * SCAN_B + threadIdx.x;
    int v = (i < n) ? g_deg[i] : 0;
    s[threadIdx.x] = v;
    __syncthreads();
    #pragma unroll
    for (int off = 1; off < SCAN_B; off <<= 1) {
        int t = (threadIdx.x >= off) ? s[threadIdx.x - off] : 0;
        __syncthreads();
        s[threadIdx.x] += t;
        __syncthreads();
    }
    if (i < n) {
        g_off[i]  = s[threadIdx.x] - v;
        g_norm[i] = rsqrtf(fmaxf((float)v, 1.0f));
    }
    if (threadIdx.x == SCAN_B - 1) g_bsum[blockIdx.x] = s[SCAN_B - 1];
}

// each block reduce-sums bsum[0..bid-1] itself; writes offsets + cursors
__global__ void scan_finish_kernel(int n, int ne) {
    __shared__ int wsum[8];
    int t = threadIdx.x;
    int v = (t < blockIdx.x) ? g_bsum[t] : 0;
    #pragma unroll
    for (int o = 16; o > 0; o >>= 1) v += __shfl_down_sync(0xffffffffu, v, o);
    if ((t & 31) == 0) wsum[t >> 5] = v;
    __syncthreads();
    int prefix = wsum[0] + wsum[1] + wsum[2] + wsum[3]
               + wsum[4] + wsum[5] + wsum[6] + wsum[7];
    int i = blockIdx.x * blockDim.x + t;
    if (i < n) {
        int o = g_off[i] + prefix;
        g_off[i] = o;
        g_cursor[i] = o;
    }
    if (i == 0) g_off[n] = ne;
}

// blocks [0, eb): permute edges into CSR + re-zero deg
// blocks [eb, ..): prescale feat*norm -> fp16 (independent of permute)
__global__ void permute_prescale_kernel(const int* __restrict__ src,
                                        const int* __restrict__ dst,
                                        const float* __restrict__ feat,
                                        int ne, int n, int eb) {
    if ((int)blockIdx.x < eb) {
        int e = blockIdx.x * blockDim.x + threadIdx.x;
        if (e < ne) {
            int d = dst[e];
            int pos = atomicAdd(&g_cursor[d], 1);
            g_csrc[pos] = src[e];
            if (e < n) g_deg[e] = 0;
        }
    } else {
        int i = (blockIdx.x - eb) * blockDim.x + threadIdx.x;
        if (i < n * 32) {
            int row = i >> 5;
            float nm = g_norm[row];
            float4 fv = __ldg((const float4*)feat + i);
            __half2 h0 = __floats2half2_rn(fv.x * nm, fv.y * nm);
            __half2 h1 = __floats2half2_rn(fv.z * nm, fv.w * nm);
            uint2 p;
            p.x = *(unsigned*)&h0;
            p.y = *(unsigned*)&h1;
            g_feath[i] = p;
        }
    }
}

// ---- aggregation: one warp per destination row, fp16 prescaled gathers ----
// Inner loop unrolled x4: 4 independent guarded loads in flight per warp.
__global__ __launch_bounds__(256) void agg_kernel(const float* __restrict__ feat0, int n) {
    int w    = (blockIdx.x * blockDim.x + threadIdx.x) >> 5;
    int lane = threadIdx.x & 31;
    if (w >= n) return;
    int beg = g_off[w];
    int end = g_off[w + 1];

    float4 acc = make_float4(0.f, 0.f, 0.f, 0.f);
    for (int j0 = beg; j0 < end; j0 += 32) {
        int jj = j0 + lane;
        int s = (jj < end) ? g_csrc[jj] : 0;
        int m = min(32, end - j0);
        for (int e = 0; e < m; e += 4) {
            uint2 p0 = make_uint2(0u, 0u), p1 = p0, p2 = p0, p3 = p0;
            {
                int ss = __shfl_sync(0xffffffffu, s, e);
                p0 = __ldg(g_feath + (size_t)ss * 32 + lane);
            }
            if (e + 1 < m) {
                int ss = __shfl_sync(0xffffffffu, s, e + 1);
                p1 = __ldg(g_feath + (size_t)ss * 32 + lane);
            }
            if (e + 2 < m) {
                int ss = __shfl_sync(0xffffffffu, s, e + 2);
                p2 = __ldg(g_feath + (size_t)ss * 32 + lane);
            }
            if (e + 3 < m) {
                int ss = __shfl_sync(0xffffffffu, s, e + 3);
                p3 = __ldg(g_feath + (size_t)ss * 32 + lane);
            }
            __half2 a01 = __hadd2(*(__half2*)&p0.x, *(__half2*)&p1.x);
            __half2 a23 = __hadd2(*(__half2*)&p2.x, *(__half2*)&p3.x);
            __half2 b01 = __hadd2(*(__half2*)&p0.y, *(__half2*)&p1.y);
            __half2 b23 = __hadd2(*(__half2*)&p2.y, *(__half2*)&p3.y);
            float2 fa = __half22float2(a01);
            float2 fb = __half22float2(a23);
            float2 fc = __half22float2(b01);
            float2 fd = __half22float2(b23);
            acc.x += fa.x + fb.x;
            acc.y += fa.y + fb.y;
            acc.z += fc.x + fd.x;
            acc.w += fc.y + fd.y;
        }
    }
    float nmd = g_norm[w] * (1.0f - ALPHA);
    float4 f0 = __ldg((const float4*)feat0 + (size_t)w * 32 + lane);
    float4 h;
    h.x = acc.x * nmd + f0.x * ALPHA;
    h.y = acc.y * nmd + f0.y * ALPHA;
    h.z = acc.z * nmd + f0.z * ALPHA;
    h.w = acc.w * nmd + f0.w * ALPHA;
    ((float4*)g_h)[(size_t)w * 32 + lane] = h;
}

// ---- tensor-core GEMM: mma.sync.m16n8k8 tf32, fp32 accumulate ----
#define GROWS 64
#define SH_PAD 132
__global__ __launch_bounds__(128) void mma_kernel(const float* __restrict__ bias,
                                                  float* __restrict__ out, int n) {
    __shared__ float sh[GROWS][SH_PAD];
    const int tid  = threadIdx.x;
    const int w    = tid >> 5;
    const int lane = tid & 31;
    const int r0   = blockIdx.x * GROWS;

    {
        int r = tid >> 1, half = tid & 1;
        int row = r0 + r;
        const float4* srcp = (const float4*)(g_h + (size_t)row * D) + half * 16;
        #pragma unroll
        for (int i = 0; i < 16; i++) {
            float4 v = (row < n) ? __ldg(srcp + i) : make_float4(0.f, 0.f, 0.f, 0.f);
            *(float4*)&sh[r][half * 64 + i * 4] = v;
        }
    }
    __syncthreads();

    float acc[16][4];
    #pragma unroll
    for (int nt = 0; nt < 16; nt++)
        #pragma unroll
        for (int i = 0; i < 4; i++) acc[nt][i] = 0.f;

    const int ra = w * 16 + (lane >> 2);
    const int ca = lane & 3;

    #pragma unroll
    for (int kt = 0; kt < 16; kt++) {
        unsigned a0 = f2tf32(sh[ra][kt * 8 + ca]);
        unsigned a1 = f2tf32(sh[ra + 8][kt * 8 + ca]);
        unsigned a2 = f2tf32(sh[ra][kt * 8 + ca + 4]);
        unsigned a3 = f2tf32(sh[ra + 8][kt * 8 + ca + 4]);
        const uint2* bp = g_wperm + (kt * 16) * 32 + lane;
        #pragma unroll
        for (int nt = 0; nt < 16; nt++) {
            uint2 b = __ldg(bp + nt * 32);
            asm volatile(
                "mma.sync.aligned.m16n8k8.row.col.f32.tf32.tf32.f32 "
                "{%0,%1,%2,%3}, {%4,%5,%6,%7}, {%8,%9}, {%0,%1,%2,%3};"
                : "+f"(acc[nt][0]), "+f"(acc[nt][1]),
                  "+f"(acc[nt][2]), "+f"(acc[nt][3])
                : "r"(a0), "r"(a1), "r"(a2), "r"(a3), "r"(b.x), "r"(b.y));
        }
    }

    const int lr   = w * 16 + (lane >> 2);
    const int row0 = r0 + lr;
    const int col0 = (lane & 3) * 2;
    #pragma unroll
    for (int nt = 0; nt < 16; nt++) {
        int col = nt * 8 + col0;
        float b0 = __ldg(&bias[col]);
        float b1 = __ldg(&bias[col + 1]);
        if (row0 < n) {
            float2 o;
            o.x = ONE_MB * sh[lr][col]     + BETA * acc[nt][0] + b0;
            o.y = ONE_MB * sh[lr][col + 1] + BETA * acc[nt][1] + b1;
            *(float2*)&out[(size_t)row0 * D + col] = o;
        }
        if (row0 + 8 < n) {
            float2 o;
            o.x = ONE_MB * sh[lr + 8][col]     + BETA * acc[nt][2] + b0;
            o.y = ONE_MB * sh[lr + 8][col + 1] + BETA * acc[nt][3] + b1;
            *(float2*)&out[(size_t)(row0 + 8) * D + col] = o;
        }
    }
}

extern "C" void kernel_launch(void* const* d_in, const int* in_sizes, int n_in,
                              void* d_out, int out_size) {
    const float* feat  = (const float*)d_in[0];
    const float* feat0 = (const float*)d_in[1];
    const float* W     = (const float*)d_in[2];
    const float* bias  = (const float*)d_in[3];
    const int*   src   = (const int*)d_in[4];
    const int*   dst   = (const int*)d_in[5];
    float* out = (float*)d_out;

    int n  = in_sizes[0] / D;
    int ne = in_sizes[4];
    int nb = (n + SCAN_B - 1) / SCAN_B;          // 196

    deg_kernel<<<(ne + 255) / 256, 256>>>(dst, W, ne);
    scan_block_kernel<<<nb, SCAN_B>>>(n);
    scan_finish_kernel<<<nb, SCAN_B>>>(n, ne);

    int eb = (ne + 255) / 256;                    // edge blocks
    int pb = (n * 32 + 255) / 256;                // prescale blocks
    permute_prescale_kernel<<<eb + pb, 256>>>(src, dst, feat, ne, n, eb);

    int agg_blocks = (n * 32 + 255) / 256;        // one warp per row
    agg_kernel<<<agg_blocks, 256>>>(feat0, n);

    mma_kernel<<<(n + GROWS - 1) / GROWS, 128>>>(bias, out, n);
}

// round 9
// speedup vs baseline: 1.3276x; 1.1930x over previous
#include <cuda_runtime.h>
#include <cuda_fp16.h>

#define D 128
#define ALPHA 0.1f
#define BETA 0.22314355131420976f        /* log(1.25) */
#define ONE_MB 0.7768564486857909f       /* 1 - BETA */
#define MAXN 50000
#define MAXE 600000
#define SCAN_B 256

__device__ int   g_deg[MAXN];            // zero at load; re-zeroed every call
__device__ int   g_off[MAXN + 1];
__device__ int   g_cursor[MAXN];
__device__ int   g_csrc[MAXE];
__device__ float g_norm[MAXN];
__device__ uint2 g_feath[MAXN * 32];     // fp16 prescaled feat: row = 32 uint2 = 128 halfs
__device__ int   g_bsum[SCAN_B];
__device__ uint2 g_wperm[16 * 16 * 32];

__device__ __forceinline__ unsigned f2tf32(float f) {
    unsigned r;
    asm("cvt.rna.tf32.f32 %0, %1;" : "=r"(r) : "f"(f));
    return r;
}

// degree count; blocks 0..31 also permute W into tf32 B-fragment order
__global__ void deg_kernel(const int* __restrict__ dst,
                           const float* __restrict__ W, int ne) {
    int e = blockIdx.x * blockDim.x + threadIdx.x;
    if (blockIdx.x < 32) {
        int t = e;                        // 8192 lanes
        int lane = t & 31, tile = t >> 5;
        int nt = tile & 15, kt = tile >> 4;
        int k = kt * 8 + (lane & 3);
        int nn = nt * 8 + (lane >> 2);
        uint2 b;
        b.x = f2tf32(W[k * D + nn]);
        b.y = f2tf32(W[(k + 4) * D + nn]);
        g_wperm[tile * 32 + lane] = b;
    }
    if (e < ne) atomicAdd(&g_deg[dst[e]], 1);
}

// block-local exclusive scan + norm
__global__ void scan_block_kernel(int n) {
    __shared__ int s[SCAN_B];
    int i = blockIdx.x * SCAN_B + threadIdx.x;
    int v = (i < n) ? g_deg[i] : 0;
    s[threadIdx.x] = v;
    __syncthreads();
    #pragma unroll
    for (int off = 1; off < SCAN_B; off <<= 1) {
        int t = (threadIdx.x >= off) ? s[threadIdx.x - off] : 0;
        __syncthreads();
        s[threadIdx.x] += t;
        __syncthreads();
    }
    if (i < n) {
        g_off[i]  = s[threadIdx.x] - v;
        g_norm[i] = rsqrtf(fmaxf((float)v, 1.0f));
    }
    if (threadIdx.x == SCAN_B - 1) g_bsum[blockIdx.x] = s[SCAN_B - 1];
}

// each block reduce-sums bsum[0..bid-1] itself; writes offsets + cursors
__global__ void scan_finish_kernel(int n, int ne) {
    __shared__ int wsum[8];
    int t = threadIdx.x;
    int v = (t < blockIdx.x) ? g_bsum[t] : 0;
    #pragma unroll
    for (int o = 16; o > 0; o >>= 1) v += __shfl_down_sync(0xffffffffu, v, o);
    if ((t & 31) == 0) wsum[t >> 5] = v;
    __syncthreads();
    int prefix = wsum[0] + wsum[1] + wsum[2] + wsum[3]
               + wsum[4] + wsum[5] + wsum[6] + wsum[7];
    int i = blockIdx.x * blockDim.x + t;
    if (i < n) {
        int o = g_off[i] + prefix;
        g_off[i] = o;
        g_cursor[i] = o;
    }
    if (i == 0) g_off[n] = ne;
}

// blocks [0, eb): permute edges into CSR + re-zero deg
// blocks [eb, ..): prescale feat*norm -> fp16
__global__ void permute_prescale_kernel(const int* __restrict__ src,
                                        const int* __restrict__ dst,
                                        const float* __restrict__ feat,
                                        int ne, int n, int eb) {
    if ((int)blockIdx.x < eb) {
        int e = blockIdx.x * blockDim.x + threadIdx.x;
        if (e < ne) {
            int d = dst[e];
            int pos = atomicAdd(&g_cursor[d], 1);
            g_csrc[pos] = src[e];
            if (e < n) g_deg[e] = 0;
        }
    } else {
        int i = (blockIdx.x - eb) * blockDim.x + threadIdx.x;
        if (i < n * 32) {
            int row = i >> 5;
            float nm = g_norm[row];
            float4 fv = __ldg((const float4*)feat + i);
            __half2 h0 = __floats2half2_rn(fv.x * nm, fv.y * nm);
            __half2 h1 = __floats2half2_rn(fv.z * nm, fv.w * nm);
            uint2 p;
            p.x = *(unsigned*)&h0;
            p.y = *(unsigned*)&h1;
            g_feath[i] = p;
        }
    }
}

// ---- FUSED aggregation + tensor-core GEMM ----
// 256 threads (8 warps), 64 rows per block.
// Phase 1: warp w aggregates rows w*8..w*8+7 (fp16 gathers, x4 unrolled) -> smem fp32.
// Phase 2: warp w computes M-tile (w&3)*16, N-half (w>>2)*64 via m16n8k8 tf32 MMA.
#define GROWS 64
#define SH_PAD 132   /* mod 32 = 4 -> conflict-free A-frag LDS */
__global__ __launch_bounds__(256) void fused_mma_kernel(const float* __restrict__ feat0,
                                                        const float* __restrict__ bias,
                                                        float* __restrict__ out, int n) {
    __shared__ float sh[GROWS][SH_PAD];
    const int tid  = threadIdx.x;
    const int w    = tid >> 5;
    const int lane = tid & 31;
    const int r0   = blockIdx.x * GROWS;

    // ---- phase 1: aggregate 8 rows per warp ----
    #pragma unroll
    for (int rr = 0; rr < 8; rr++) {
        int lrow = w * 8 + rr;
        int row  = r0 + lrow;
        float4 acc = make_float4(0.f, 0.f, 0.f, 0.f);
        if (row < n) {
            int beg = g_off[row];
            int end = g_off[row + 1];
            for (int j0 = beg; j0 < end; j0 += 32) {
                int jj = j0 + lane;
                int s = (jj < end) ? g_csrc[jj] : 0;
                int m = min(32, end - j0);
                for (int e = 0; e < m; e += 4) {
                    uint2 p0 = make_uint2(0u, 0u), p1 = p0, p2 = p0, p3 = p0;
                    {
                        int ss = __shfl_sync(0xffffffffu, s, e);
                        p0 = __ldg(g_feath + (size_t)ss * 32 + lane);
                    }
                    if (e + 1 < m) {
                        int ss = __shfl_sync(0xffffffffu, s, e + 1);
                        p1 = __ldg(g_feath + (size_t)ss * 32 + lane);
                    }
                    if (e + 2 < m) {
                        int ss = __shfl_sync(0xffffffffu, s, e + 2);
                        p2 = __ldg(g_feath + (size_t)ss * 32 + lane);
                    }
                    if (e + 3 < m) {
                        int ss = __shfl_sync(0xffffffffu, s, e + 3);
                        p3 = __ldg(g_feath + (size_t)ss * 32 + lane);
                    }
                    __half2 a01 = __hadd2(*(__half2*)&p0.x, *(__half2*)&p1.x);
                    __half2 a23 = __hadd2(*(__half2*)&p2.x, *(__half2*)&p3.x);
                    __half2 b01 = __hadd2(*(__half2*)&p0.y, *(__half2*)&p1.y);
                    __half2 b23 = __hadd2(*(__half2*)&p2.y, *(__half2*)&p3.y);
                    float2 fa = __half22float2(a01);
                    float2 fb = __half22float2(a23);
                    float2 fc = __half22float2(b01);
                    float2 fd = __half22float2(b23);
                    acc.x += fa.x + fb.x;
                    acc.y += fa.y + fb.y;
                    acc.z += fc.x + fd.x;
                    acc.w += fc.y + fd.y;
                }
            }
            float nmd = g_norm[row] * (1.0f - ALPHA);
            float4 f0 = __ldg((const float4*)feat0 + (size_t)row * 32 + lane);
            acc.x = acc.x * nmd + f0.x * ALPHA;
            acc.y = acc.y * nmd + f0.y * ALPHA;
            acc.z = acc.z * nmd + f0.z * ALPHA;
            acc.w = acc.w * nmd + f0.w * ALPHA;
        }
        *(float4*)&sh[lrow][lane * 4] = acc;
    }
    __syncthreads();

    // ---- phase 2: MMA. warp -> (M-tile, N-half) ----
    const int mw    = w & 3;              // M-tile 16 rows
    const int nhalf = w >> 2;             // N-half 64 cols
    float acc[8][4];
    #pragma unroll
    for (int nt = 0; nt < 8; nt++)
        #pragma unroll
        for (int i = 0; i < 4; i++) acc[nt][i] = 0.f;

    const int ra = mw * 16 + (lane >> 2);
    const int ca = lane & 3;

    #pragma unroll
    for (int kt = 0; kt < 16; kt++) {
        unsigned a0 = f2tf32(sh[ra][kt * 8 + ca]);
        unsigned a1 = f2tf32(sh[ra + 8][kt * 8 + ca]);
        unsigned a2 = f2tf32(sh[ra][kt * 8 + ca + 4]);
        unsigned a3 = f2tf32(sh[ra + 8][kt * 8 + ca + 4]);
        const uint2* bp = g_wperm + (kt * 16 + nhalf * 8) * 32 + lane;
        #pragma unroll
        for (int nt = 0; nt < 8; nt++) {
            uint2 b = __ldg(bp + nt * 32);
            asm volatile(
                "mma.sync.aligned.m16n8k8.row.col.f32.tf32.tf32.f32 "
                "{%0,%1,%2,%3}, {%4,%5,%6,%7}, {%8,%9}, {%0,%1,%2,%3};"
                : "+f"(acc[nt][0]), "+f"(acc[nt][1]),
                  "+f"(acc[nt][2]), "+f"(acc[nt][3])
                : "r"(a0), "r"(a1), "r"(a2), "r"(a3), "r"(b.x), "r"(b.y));
        }
    }

    // epilogue
    const int lr   = mw * 16 + (lane >> 2);
    const int row0 = r0 + lr;
    const int col0 = (lane & 3) * 2;
    #pragma unroll
    for (int nt = 0; nt < 8; nt++) {
        int col = nhalf * 64 + nt * 8 + col0;
        float b0 = __ldg(&bias[col]);
        float b1 = __ldg(&bias[col + 1]);
        if (row0 < n) {
            float2 o;
            o.x = ONE_MB * sh[lr][col]     + BETA * acc[nt][0] + b0;
            o.y = ONE_MB * sh[lr][col + 1] + BETA * acc[nt][1] + b1;
            *(float2*)&out[(size_t)row0 * D + col] = o;
        }
        if (row0 + 8 < n) {
            float2 o;
            o.x = ONE_MB * sh[lr + 8][col]     + BETA * acc[nt][2] + b0;
            o.y = ONE_MB * sh[lr + 8][col + 1] + BETA * acc[nt][3] + b1;
            *(float2*)&out[(size_t)(row0 + 8) * D + col] = o;
        }
    }
}

extern "C" void kernel_launch(void* const* d_in, const int* in_sizes, int n_in,
                              void* d_out, int out_size) {
    const float* feat  = (const float*)d_in[0];
    const float* feat0 = (const float*)d_in[1];
    const float* W     = (const float*)d_in[2];
    const float* bias  = (const float*)d_in[3];
    const int*   src   = (const int*)d_in[4];
    const int*   dst   = (const int*)d_in[5];
    float* out = (float*)d_out;

    int n  = in_sizes[0] / D;
    int ne = in_sizes[4];
    int nb = (n + SCAN_B - 1) / SCAN_B;          // 196

    deg_kernel<<<(ne + 255) / 256, 256>>>(dst, W, ne);
    scan_block_kernel<<<nb, SCAN_B>>>(n);
    scan_finish_kernel<<<nb, SCAN_B>>>(n, ne);

    int eb = (ne + 255) / 256;                    // edge blocks
    int pb = (n * 32 + 255) / 256;                // prescale blocks
    permute_prescale_kernel<<<eb + pb, 256>>>(src, dst, feat, ne, n, eb);

    fused_mma_kernel<<<(n + GROWS - 1) / GROWS, 256>>>(feat0, bias, out, n);
}

// round 10
// speedup vs baseline: 1.3316x; 1.0030x over previous
#include <cuda_runtime.h>
#include <cuda_fp16.h>

#define D 128
#define ALPHA 0.1f
#define BETA 0.22314355131420976f        /* log(1.25) */
#define ONE_MB 0.7768564486857909f       /* 1 - BETA */
#define MAXN 50000
#define MAXE 600000
#define SCAN_B 256
#define MAXNB 256                        /* max scan blocks (196 actual) */

__device__ int      g_deg[MAXN];         // zero at load; re-zeroed every call
__device__ int      g_off[MAXN + 1];
__device__ int      g_cursor[MAXN];
__device__ int      g_csrc[MAXE];
__device__ float    g_norm[MAXN];
__device__ uint2    g_feath[MAXN * 32];  // fp16 prescaled feat: row = 32 uint2
__device__ int      g_bsum[MAXNB];
__device__ uint2    g_wperm[16 * 16 * 32];
__device__ unsigned g_scan_ctr;          // zeroed by deg_kernel each call

__device__ __forceinline__ unsigned f2tf32(float f) {
    unsigned r;
    asm("cvt.rna.tf32.f32 %0, %1;" : "=r"(r) : "f"(f));
    return r;
}

// degree count (4 edges/thread, independent REDs); blocks 0..31 also permute W
__global__ void deg_kernel(const int* __restrict__ dst,
                           const float* __restrict__ W, int ne) {
    int tid = threadIdx.x;
    if (blockIdx.x == 0 && tid == 0) g_scan_ctr = 0;   // reset scan barrier
    if (blockIdx.x < 32) {
        int t = blockIdx.x * 256 + tid;  // 8192 lanes
        int lane = t & 31, tile = t >> 5;
        int nt = tile & 15, kt = tile >> 4;
        int k = kt * 8 + (lane & 3);
        int nn = nt * 8 + (lane >> 2);
        uint2 b;
        b.x = f2tf32(W[k * D + nn]);
        b.y = f2tf32(W[(k + 4) * D + nn]);
        g_wperm[tile * 32 + lane] = b;
    }
    int base = blockIdx.x * 1024 + tid;
    int d0 = -1, d1 = -1, d2 = -1, d3 = -1;
    if (base           < ne) d0 = dst[base];
    if (base + 256     < ne) d1 = dst[base + 256];
    if (base + 512     < ne) d2 = dst[base + 512];
    if (base + 768     < ne) d3 = dst[base + 768];
    if (d0 >= 0) atomicAdd(&g_deg[d0], 1);
    if (d1 >= 0) atomicAdd(&g_deg[d1], 1);
    if (d2 >= 0) atomicAdd(&g_deg[d2], 1);
    if (d3 >= 0) atomicAdd(&g_deg[d3], 1);
}

// single scan kernel: local scan + norm, grid barrier, cross-block prefix
__global__ __launch_bounds__(SCAN_B) void scan_kernel(int n, int ne) {
    __shared__ int s[SCAN_B];
    __shared__ int wsum[SCAN_B / 32];
    const int tid = threadIdx.x;
    const int bid = blockIdx.x;
    const int i = bid * SCAN_B + tid;

    int v = (i < n) ? g_deg[i] : 0;
    s[tid] = v;
    __syncthreads();
    #pragma unroll
    for (int off = 1; off < SCAN_B; off <<= 1) {
        int t = (tid >= off) ? s[tid - off] : 0;
        __syncthreads();
        s[tid] += t;
        __syncthreads();
    }
    int local_ex = s[tid] - v;
    if (i < n) g_norm[i] = rsqrtf(fmaxf((float)v, 1.0f));
    if (tid == SCAN_B - 1) g_bsum[bid] = s[SCAN_B - 1];

    // grid barrier (all blocks co-resident: <=2 per SM)
    __syncthreads();
    __threadfence();
    if (tid == 0) {
        atomicAdd(&g_scan_ctr, 1u);
        while (*(volatile unsigned*)&g_scan_ctr < gridDim.x) { }
    }
    __syncthreads();
    __threadfence();

    // prefix = sum of bsum[0..bid-1]  (gridDim <= 256)
    int pv = (tid < bid) ? g_bsum[tid] : 0;
    #pragma unroll
    for (int o = 16; o > 0; o >>= 1) pv += __shfl_down_sync(0xffffffffu, pv, o);
    if ((tid & 31) == 0) wsum[tid >> 5] = pv;
    __syncthreads();
    int prefix = 0;
    #pragma unroll
    for (int j = 0; j < SCAN_B / 32; j++) prefix += wsum[j];

    if (i < n) {
        int o = local_ex + prefix;
        g_off[i] = o;
        g_cursor[i] = o;
    }
    if (i == 0) g_off[n] = ne;
}

// blocks [0, eb): permute 4 edges/thread (independent atomic chains) + re-zero deg
// blocks [eb, ..): prescale feat*norm -> fp16
__global__ void permute_prescale_kernel(const int* __restrict__ src,
                                        const int* __restrict__ dst,
                                        const float* __restrict__ feat,
                                        int ne, int n, int eb) {
    if ((int)blockIdx.x < eb) {
        int tid = threadIdx.x;
        int base = blockIdx.x * 1024 + tid;
        int s0 = 0, s1 = 0, s2 = 0, s3 = 0;
        int d0 = -1, d1 = -1, d2 = -1, d3 = -1;
        if (base           < ne) { s0 = src[base];       d0 = dst[base]; }
        if (base + 256     < ne) { s1 = src[base + 256]; d1 = dst[base + 256]; }
        if (base + 512     < ne) { s2 = src[base + 512]; d2 = dst[base + 512]; }
        if (base + 768     < ne) { s3 = src[base + 768]; d3 = dst[base + 768]; }
        int p0 = (d0 >= 0) ? atomicAdd(&g_cursor[d0], 1) : 0;
        int p1 = (d1 >= 0) ? atomicAdd(&g_cursor[d1], 1) : 0;
        int p2 = (d2 >= 0) ? atomicAdd(&g_cursor[d2], 1) : 0;
        int p3 = (d3 >= 0) ? atomicAdd(&g_cursor[d3], 1) : 0;
        if (d0 >= 0) g_csrc[p0] = s0;
        if (d1 >= 0) g_csrc[p1] = s1;
        if (d2 >= 0) g_csrc[p2] = s2;
        if (d3 >= 0) g_csrc[p3] = s3;
        // re-zero deg for next replay (edge-index space covers node space)
        if (base < n)       g_deg[base] = 0;
        if (base + 256 < n) g_deg[base + 256] = 0;
        if (base + 512 < n) g_deg[base + 512] = 0;
        if (base + 768 < n) g_deg[base + 768] = 0;
    } else {
        int i = (blockIdx.x - eb) * blockDim.x + threadIdx.x;
        if (i < n * 32) {
            int row = i >> 5;
            float nm = g_norm[row];
            float4 fv = __ldg((const float4*)feat + i);
            __half2 h0 = __floats2half2_rn(fv.x * nm, fv.y * nm);
            __half2 h1 = __floats2half2_rn(fv.z * nm, fv.w * nm);
            uint2 p;
            p.x = *(unsigned*)&h0;
            p.y = *(unsigned*)&h1;
            g_feath[i] = p;
        }
    }
}

// ---- FUSED aggregation + tensor-core GEMM (unchanged from r9) ----
#define GROWS 64
#define SH_PAD 132
__global__ __launch_bounds__(256) void fused_mma_kernel(const float* __restrict__ feat0,
                                                        const float* __restrict__ bias,
                                                        float* __restrict__ out, int n) {
    __shared__ float sh[GROWS][SH_PAD];
    const int tid  = threadIdx.x;
    const int w    = tid >> 5;
    const int lane = tid & 31;
    const int r0   = blockIdx.x * GROWS;

    #pragma unroll
    for (int rr = 0; rr < 8; rr++) {
        int lrow = w * 8 + rr;
        int row  = r0 + lrow;
        float4 acc = make_float4(0.f, 0.f, 0.f, 0.f);
        if (row < n) {
            int beg = g_off[row];
            int end = g_off[row + 1];
            for (int j0 = beg; j0 < end; j0 += 32) {
                int jj = j0 + lane;
                int s = (jj < end) ? g_csrc[jj] : 0;
                int m = min(32, end - j0);
                for (int e = 0; e < m; e += 4) {
                    uint2 p0 = make_uint2(0u, 0u), p1 = p0, p2 = p0, p3 = p0;
                    {
                        int ss = __shfl_sync(0xffffffffu, s, e);
                        p0 = __ldg(g_feath + (size_t)ss * 32 + lane);
                    }
                    if (e + 1 < m) {
                        int ss = __shfl_sync(0xffffffffu, s, e + 1);
                        p1 = __ldg(g_feath + (size_t)ss * 32 + lane);
                    }
                    if (e + 2 < m) {
                        int ss = __shfl_sync(0xffffffffu, s, e + 2);
                        p2 = __ldg(g_feath + (size_t)ss * 32 + lane);
                    }
                    if (e + 3 < m) {
                        int ss = __shfl_sync(0xffffffffu, s, e + 3);
                        p3 = __ldg(g_feath + (size_t)ss * 32 + lane);
                    }
                    __half2 a01 = __hadd2(*(__half2*)&p0.x, *(__half2*)&p1.x);
                    __half2 a23 = __hadd2(*(__half2*)&p2.x, *(__half2*)&p3.x);
                    __half2 b01 = __hadd2(*(__half2*)&p0.y, *(__half2*)&p1.y);
                    __half2 b23 = __hadd2(*(__half2*)&p2.y, *(__half2*)&p3.y);
                    float2 fa = __half22float2(a01);
                    float2 fb = __half22float2(a23);
                    float2 fc = __half22float2(b01);
                    float2 fd = __half22float2(b23);
                    acc.x += fa.x + fb.x;
                    acc.y += fa.y + fb.y;
                    acc.z += fc.x + fd.x;
                    acc.w += fc.y + fd.y;
                }
            }
            float nmd = g_norm[row] * (1.0f - ALPHA);
            float4 f0 = __ldg((const float4*)feat0 + (size_t)row * 32 + lane);
            acc.x = acc.x * nmd + f0.x * ALPHA;
            acc.y = acc.y * nmd + f0.y * ALPHA;
            acc.z = acc.z * nmd + f0.z * ALPHA;
            acc.w = acc.w * nmd + f0.w * ALPHA;
        }
        *(float4*)&sh[lrow][lane * 4] = acc;
    }
    __syncthreads();

    const int mw    = w & 3;
    const int nhalf = w >> 2;
    float acc[8][4];
    #pragma unroll
    for (int nt = 0; nt < 8; nt++)
        #pragma unroll
        for (int i = 0; i < 4; i++) acc[nt][i] = 0.f;

    const int ra = mw * 16 + (lane >> 2);
    const int ca = lane & 3;

    #pragma unroll
    for (int kt = 0; kt < 16; kt++) {
        unsigned a0 = f2tf32(sh[ra][kt * 8 + ca]);
        unsigned a1 = f2tf32(sh[ra + 8][kt * 8 + ca]);
        unsigned a2 = f2tf32(sh[ra][kt * 8 + ca + 4]);
        unsigned a3 = f2tf32(sh[ra + 8][kt * 8 + ca + 4]);
        const uint2* bp = g_wperm + (kt * 16 + nhalf * 8) * 32 + lane;
        #pragma unroll
        for (int nt = 0; nt < 8; nt++) {
            uint2 b = __ldg(bp + nt * 32);
            asm volatile(
                "mma.sync.aligned.m16n8k8.row.col.f32.tf32.tf32.f32 "
                "{%0,%1,%2,%3}, {%4,%5,%6,%7}, {%8,%9}, {%0,%1,%2,%3};"
                : "+f"(acc[nt][0]), "+f"(acc[nt][1]),
                  "+f"(acc[nt][2]), "+f"(acc[nt][3])
                : "r"(a0), "r"(a1), "r"(a2), "r"(a3), "r"(b.x), "r"(b.y));
        }
    }

    const int lr   = mw * 16 + (lane >> 2);
    const int row0 = r0 + lr;
    const int col0 = (lane & 3) * 2;
    #pragma unroll
    for (int nt = 0; nt < 8; nt++) {
        int col = nhalf * 64 + nt * 8 + col0;
        float b0 = __ldg(&bias[col]);
        float b1 = __ldg(&bias[col + 1]);
        if (row0 < n) {
            float2 o;
            o.x = ONE_MB * sh[lr][col]     + BETA * acc[nt][0] + b0;
            o.y = ONE_MB * sh[lr][col + 1] + BETA * acc[nt][1] + b1;
            *(float2*)&out[(size_t)row0 * D + col] = o;
        }
        if (row0 + 8 < n) {
            float2 o;
            o.x = ONE_MB * sh[lr + 8][col]     + BETA * acc[nt][2] + b0;
            o.y = ONE_MB * sh[lr + 8][col + 1] + BETA * acc[nt][3] + b1;
            *(float2*)&out[(size_t)(row0 + 8) * D + col] = o;
        }
    }
}

extern "C" void kernel_launch(void* const* d_in, const int* in_sizes, int n_in,
                              void* d_out, int out_size) {
    const float* feat  = (const float*)d_in[0];
    const float* feat0 = (const float*)d_in[1];
    const float* W     = (const float*)d_in[2];
    const float* bias  = (const float*)d_in[3];
    const int*   src   = (const int*)d_in[4];
    const int*   dst   = (const int*)d_in[5];
    float* out = (float*)d_out;

    int n  = in_sizes[0] / D;
    int ne = in_sizes[4];
    int nb = (n + SCAN_B - 1) / SCAN_B;          // 196 scan blocks

    int eb4 = (ne + 1023) / 1024;                 // 4-edges-per-thread blocks (586)
    int degb = (eb4 > 32) ? eb4 : 32;             // ensure wconv lanes exist

    deg_kernel<<<degb, 256>>>(dst, W, ne);
    scan_kernel<<<nb, SCAN_B>>>(n, ne);

    int pb = (n * 32 + 255) / 256;                // prescale blocks
    permute_prescale_kernel<<<eb4 + pb, 256>>>(src, dst, feat, ne, n, eb4);

    fused_mma_kernel<<<(n + GROWS - 1) / GROWS, 256>>>(feat0, bias, out, n);
}

// round 11
// speedup vs baseline: 1.5234x; 1.1441x over previous
#include <cuda_runtime.h>
#include <cuda_fp16.h>

#define D 128
#define ALPHA 0.1f
#define BETA 0.22314355131420976f        /* log(1.25) */
#define ONE_MB 0.7768564486857909f       /* 1 - BETA */
#define MAXN 50000
#define MAXE 600000
#define SCAN_B 256
#define MAXNB 256

__device__ int      g_deg[MAXN];         // zero at load; re-zeroed every call
__device__ int      g_off[MAXN + 1];
__device__ int      g_cursor[MAXN];
__device__ int      g_csrc[MAXE];
__device__ float    g_norm[MAXN];
__device__ uint2    g_feath[MAXN * 32];  // fp16 prescaled feat: row = 32 uint2
__device__ int      g_bsum[MAXNB];
__device__ uint2    g_wperm[16 * 16 * 32];
__device__ unsigned g_scan_ctr;          // zeroed by deg_kernel each call

__device__ __forceinline__ unsigned f2tf32(float f) {
    unsigned r;
    asm("cvt.rna.tf32.f32 %0, %1;" : "=r"(r) : "f"(f));
    return r;
}

// degree count (4 edges/thread); blocks 0..31 also permute W into B-frag order
__global__ void deg_kernel(const int* __restrict__ dst,
                           const float* __restrict__ W, int ne) {
    int tid = threadIdx.x;
    if (blockIdx.x == 0 && tid == 0) g_scan_ctr = 0;
    if (blockIdx.x < 32) {
        int t = blockIdx.x * 256 + tid;
        int lane = t & 31, tile = t >> 5;
        int nt = tile & 15, kt = tile >> 4;
        int k = kt * 8 + (lane & 3);
        int nn = nt * 8 + (lane >> 2);
        uint2 b;
        b.x = f2tf32(W[k * D + nn]);
        b.y = f2tf32(W[(k + 4) * D + nn]);
        g_wperm[tile * 32 + lane] = b;
    }
    int base = blockIdx.x * 1024 + tid;
    int d0 = -1, d1 = -1, d2 = -1, d3 = -1;
    if (base           < ne) d0 = dst[base];
    if (base + 256     < ne) d1 = dst[base + 256];
    if (base + 512     < ne) d2 = dst[base + 512];
    if (base + 768     < ne) d3 = dst[base + 768];
    if (d0 >= 0) atomicAdd(&g_deg[d0], 1);
    if (d1 >= 0) atomicAdd(&g_deg[d1], 1);
    if (d2 >= 0) atomicAdd(&g_deg[d2], 1);
    if (d3 >= 0) atomicAdd(&g_deg[d3], 1);
}

// single scan kernel: local scan + norm, grid barrier, cross-block prefix
__global__ __launch_bounds__(SCAN_B) void scan_kernel(int n, int ne) {
    __shared__ int s[SCAN_B];
    __shared__ int wsum[SCAN_B / 32];
    const int tid = threadIdx.x;
    const int bid = blockIdx.x;
    const int i = bid * SCAN_B + tid;

    int v = (i < n) ? g_deg[i] : 0;
    s[tid] = v;
    __syncthreads();
    #pragma unroll
    for (int off = 1; off < SCAN_B; off <<= 1) {
        int t = (tid >= off) ? s[tid - off] : 0;
        __syncthreads();
        s[tid] += t;
        __syncthreads();
    }
    int local_ex = s[tid] - v;
    if (i < n) g_norm[i] = rsqrtf(fmaxf((float)v, 1.0f));
    if (tid == SCAN_B - 1) g_bsum[bid] = s[SCAN_B - 1];

    __syncthreads();
    __threadfence();
    if (tid == 0) {
        atomicAdd(&g_scan_ctr, 1u);
        while (*(volatile unsigned*)&g_scan_ctr < gridDim.x) { }
    }
    __syncthreads();
    __threadfence();

    int pv = (tid < bid) ? g_bsum[tid] : 0;
    #pragma unroll
    for (int o = 16; o > 0; o >>= 1) pv += __shfl_down_sync(0xffffffffu, pv, o);
    if ((tid & 31) == 0) wsum[tid >> 5] = pv;
    __syncthreads();
    int prefix = 0;
    #pragma unroll
    for (int j = 0; j < SCAN_B / 32; j++) prefix += wsum[j];

    if (i < n) {
        int o = local_ex + prefix;
        g_off[i] = o;
        g_cursor[i] = o;
    }
    if (i == 0) g_off[n] = ne;
}

// blocks [0, eb): permute 4 edges/thread + re-zero deg; rest: prescale fp16
__global__ void permute_prescale_kernel(const int* __restrict__ src,
                                        const int* __restrict__ dst,
                                        const float* __restrict__ feat,
                                        int ne, int n, int eb) {
    if ((int)blockIdx.x < eb) {
        int tid = threadIdx.x;
        int base = blockIdx.x * 1024 + tid;
        int s0 = 0, s1 = 0, s2 = 0, s3 = 0;
        int d0 = -1, d1 = -1, d2 = -1, d3 = -1;
        if (base           < ne) { s0 = src[base];       d0 = dst[base]; }
        if (base + 256     < ne) { s1 = src[base + 256]; d1 = dst[base + 256]; }
        if (base + 512     < ne) { s2 = src[base + 512]; d2 = dst[base + 512]; }
        if (base + 768     < ne) { s3 = src[base + 768]; d3 = dst[base + 768]; }
        int p0 = (d0 >= 0) ? atomicAdd(&g_cursor[d0], 1) : 0;
        int p1 = (d1 >= 0) ? atomicAdd(&g_cursor[d1], 1) : 0;
        int p2 = (d2 >= 0) ? atomicAdd(&g_cursor[d2], 1) : 0;
        int p3 = (d3 >= 0) ? atomicAdd(&g_cursor[d3], 1) : 0;
        if (d0 >= 0) g_csrc[p0] = s0;
        if (d1 >= 0) g_csrc[p1] = s1;
        if (d2 >= 0) g_csrc[p2] = s2;
        if (d3 >= 0) g_csrc[p3] = s3;
        if (base < n)       g_deg[base] = 0;
        if (base + 256 < n) g_deg[base + 256] = 0;
        if (base + 512 < n) g_deg[base + 512] = 0;
        if (base + 768 < n) g_deg[base + 768] = 0;
    } else {
        int i = (blockIdx.x - eb) * blockDim.x + threadIdx.x;
        if (i < n * 32) {
            int row = i >> 5;
            float nm = g_norm[row];
            float4 fv = __ldg((const float4*)feat + i);
            __half2 h0 = __floats2half2_rn(fv.x * nm, fv.y * nm);
            __half2 h1 = __floats2half2_rn(fv.z * nm, fv.w * nm);
            uint2 p;
            p.x = *(unsigned*)&h0;
            p.y = *(unsigned*)&h1;
            g_feath[i] = p;
        }
    }
}

// ---- FUSED aggregation + tensor-core GEMM, 512 threads / 16 warps ----
// Phase 1: warp w aggregates rows w*4..w*4+3 -> smem fp32 tile (64 x 128).
// Phase 2: warp w -> M-tile (w&3)*16, N-quarter (w>>2)*32; acc[4][4] = 16 regs.
#define GROWS 64
#define SH_PAD 132   /* mod 32 = 4 -> conflict-free A-frag LDS */
__global__ __launch_bounds__(512, 3) void fused_mma_kernel(const float* __restrict__ feat0,
                                                           const float* __restrict__ bias,
                                                           float* __restrict__ out, int n) {
    __shared__ float sh[GROWS][SH_PAD];
    const int tid  = threadIdx.x;
    const int w    = tid >> 5;
    const int lane = tid & 31;
    const int r0   = blockIdx.x * GROWS;

    // ---- phase 1: aggregate 4 rows per warp ----
    #pragma unroll
    for (int rr = 0; rr < 4; rr++) {
        int lrow = w * 4 + rr;
        int row  = r0 + lrow;
        float4 acc = make_float4(0.f, 0.f, 0.f, 0.f);
        if (row < n) {
            int beg = g_off[row];
            int end = g_off[row + 1];
            for (int j0 = beg; j0 < end; j0 += 32) {
                int jj = j0 + lane;
                int s = (jj < end) ? g_csrc[jj] : 0;
                int m = min(32, end - j0);
                for (int e = 0; e < m; e += 4) {
                    uint2 p0 = make_uint2(0u, 0u), p1 = p0, p2 = p0, p3 = p0;
                    {
                        int ss = __shfl_sync(0xffffffffu, s, e);
                        p0 = __ldg(g_feath + (size_t)ss * 32 + lane);
                    }
                    if (e + 1 < m) {
                        int ss = __shfl_sync(0xffffffffu, s, e + 1);
                        p1 = __ldg(g_feath + (size_t)ss * 32 + lane);
                    }
                    if (e + 2 < m) {
                        int ss = __shfl_sync(0xffffffffu, s, e + 2);
                        p2 = __ldg(g_feath + (size_t)ss * 32 + lane);
                    }
                    if (e + 3 < m) {
                        int ss = __shfl_sync(0xffffffffu, s, e + 3);
                        p3 = __ldg(g_feath + (size_t)ss * 32 + lane);
                    }
                    __half2 a01 = __hadd2(*(__half2*)&p0.x, *(__half2*)&p1.x);
                    __half2 a23 = __hadd2(*(__half2*)&p2.x, *(__half2*)&p3.x);
                    __half2 b01 = __hadd2(*(__half2*)&p0.y, *(__half2*)&p1.y);
                    __half2 b23 = __hadd2(*(__half2*)&p2.y, *(__half2*)&p3.y);
                    float2 fa = __half22float2(a01);
                    float2 fb = __half22float2(a23);
                    float2 fc = __half22float2(b01);
                    float2 fd = __half22float2(b23);
                    acc.x += fa.x + fb.x;
                    acc.y += fa.y + fb.y;
                    acc.z += fc.x + fd.x;
                    acc.w += fc.y + fd.y;
                }
            }
            float nmd = g_norm[row] * (1.0f - ALPHA);
            float4 f0 = __ldg((const float4*)feat0 + (size_t)row * 32 + lane);
            acc.x = acc.x * nmd + f0.x * ALPHA;
            acc.y = acc.y * nmd + f0.y * ALPHA;
            acc.z = acc.z * nmd + f0.z * ALPHA;
            acc.w = acc.w * nmd + f0.w * ALPHA;
        }
        *(float4*)&sh[lrow][lane * 4] = acc;
    }
    __syncthreads();

    // ---- phase 2: MMA. warp -> (M-tile, N-quarter) ----
    const int mw = w & 3;                 // M-tile: 16 rows
    const int nq = w >> 2;                // N-quarter: 32 cols
    float acc[4][4];
    #pragma unroll
    for (int nt = 0; nt < 4; nt++)
        #pragma unroll
        for (int i = 0; i < 4; i++) acc[nt][i] = 0.f;

    const int ra = mw * 16 + (lane >> 2);
    const int ca = lane & 3;

    #pragma unroll
    for (int kt = 0; kt < 16; kt++) {
        unsigned a0 = f2tf32(sh[ra][kt * 8 + ca]);
        unsigned a1 = f2tf32(sh[ra + 8][kt * 8 + ca]);
        unsigned a2 = f2tf32(sh[ra][kt * 8 + ca + 4]);
        unsigned a3 = f2tf32(sh[ra + 8][kt * 8 + ca + 4]);
        const uint2* bp = g_wperm + (kt * 16 + nq * 4) * 32 + lane;
        #pragma unroll
        for (int nt = 0; nt < 4; nt++) {
            uint2 b = __ldg(bp + nt * 32);
            asm volatile(
                "mma.sync.aligned.m16n8k8.row.col.f32.tf32.tf32.f32 "
                "{%0,%1,%2,%3}, {%4,%5,%6,%7}, {%8,%9}, {%0,%1,%2,%3};"
                : "+f"(acc[nt][0]), "+f"(acc[nt][1]),
                  "+f"(acc[nt][2]), "+f"(acc[nt][3])
                : "r"(a0), "r"(a1), "r"(a2), "r"(a3), "r"(b.x), "r"(b.y));
        }
    }

    // epilogue: out = (1-beta)*h + beta*acc + bias
    const int lr   = mw * 16 + (lane >> 2);
    const int row0 = r0 + lr;
    const int col0 = (lane & 3) * 2;
    #pragma unroll
    for (int nt = 0; nt < 4; nt++) {
        int col = nq * 32 + nt * 8 + col0;
        float b0 = __ldg(&bias[col]);
        float b1 = __ldg(&bias[col + 1]);
        if (row0 < n) {
            float2 o;
            o.x = ONE_MB * sh[lr][col]     + BETA * acc[nt][0] + b0;
            o.y = ONE_MB * sh[lr][col + 1] + BETA * acc[nt][1] + b1;
            *(float2*)&out[(size_t)row0 * D + col] = o;
        }
        if (row0 + 8 < n) {
            float2 o;
            o.x = ONE_MB * sh[lr + 8][col]     + BETA * acc[nt][2] + b0;
            o.y = ONE_MB * sh[lr + 8][col + 1] + BETA * acc[nt][3] + b1;
            *(float2*)&out[(size_t)(row0 + 8) * D + col] = o;
        }
    }
}

extern "C" void kernel_launch(void* const* d_in, const int* in_sizes, int n_in,
                              void* d_out, int out_size) {
    const float* feat  = (const float*)d_in[0];
    const float* feat0 = (const float*)d_in[1];
    const float* W     = (const float*)d_in[2];
    const float* bias  = (const float*)d_in[3];
    const int*   src   = (const int*)d_in[4];
    const int*   dst   = (const int*)d_in[5];
    float* out = (float*)d_out;

    int n  = in_sizes[0] / D;
    int ne = in_sizes[4];
    int nb = (n + SCAN_B - 1) / SCAN_B;          // 196 scan blocks

    int eb4 = (ne + 1023) / 1024;                 // 4-edges-per-thread blocks
    int degb = (eb4 > 32) ? eb4 : 32;

    deg_kernel<<<degb, 256>>>(dst, W, ne);
    scan_kernel<<<nb, SCAN_B>>>(n, ne);

    int pb = (n * 32 + 255) / 256;                // prescale blocks
    permute_prescale_kernel<<<eb4 + pb, 256>>>(src, dst, feat, ne, n, eb4);

    fused_mma_kernel<<<(n + GROWS - 1) / GROWS, 512>>>(feat0, bias, out, n);
}